// round 1
// baseline (speedup 1.0000x reference)
#include <cuda_runtime.h>
#include <cstdint>
#include <cstddef>

#define Nn 8192
#define Kk 64
#define HASHSZ 8192
#define LISTCAP 2560

// ---------------------------------------------------------------------------
// device globals (scratch; no allocation allowed)
// ---------------------------------------------------------------------------
__device__ float g_s[Nn];

// ---------------------------------------------------------------------------
// Kernel 1: fused GEMV (y = sigmoid(W @ (0.95*s) + 0.05*noise)) and
//           decay copy W_out = clip(W * 0.999, -2, 2).
// One warp per row. Reads W once (256MB), writes W_out once (256MB).
// ---------------------------------------------------------------------------
__global__ void __launch_bounds__(256) gemv_decay_kernel(
    const float* __restrict__ W,
    const float* __restrict__ s_in,
    const float* __restrict__ noise,
    float* __restrict__ Wout)
{
    const int warp = (blockIdx.x * blockDim.x + threadIdx.x) >> 5;
    const int lane = threadIdx.x & 31;
    if (warp >= Nn) return;

    const float4* wrow  = reinterpret_cast<const float4*>(W    + (size_t)warp * Nn);
    float4*       worow = reinterpret_cast<float4*>      (Wout + (size_t)warp * Nn);
    const float4* s4    = reinterpret_cast<const float4*>(s_in);

    float acc = 0.f;
    #pragma unroll 4
    for (int k = lane; k < Nn / 4; k += 32) {
        float4 w  = wrow[k];
        float4 sv = __ldg(&s4[k]);
        acc += w.x * (sv.x * 0.95f) + w.y * (sv.y * 0.95f)
             + w.z * (sv.z * 0.95f) + w.w * (sv.w * 0.95f);
        float4 o;
        o.x = fminf(fmaxf(w.x * 0.999f, -2.f), 2.f);
        o.y = fminf(fmaxf(w.y * 0.999f, -2.f), 2.f);
        o.z = fminf(fmaxf(w.z * 0.999f, -2.f), 2.f);
        o.w = fminf(fmaxf(w.w * 0.999f, -2.f), 2.f);
        worow[k] = o;
    }
    #pragma unroll
    for (int off = 16; off; off >>= 1)
        acc += __shfl_xor_sync(0xFFFFFFFFu, acc, off);
    if (lane == 0) {
        float z = acc + 0.05f * noise[warp];
        g_s[warp] = 1.0f / (1.0f + expf(-z));
    }
}

// ---------------------------------------------------------------------------
// Scan kernel helpers
// ---------------------------------------------------------------------------
struct alignas(16) ScanSmem {
    float row[2][Nn];                       // double-buffered W rows (TMA dst)
    unsigned long long warpTop[32][6];      // per-warp top6 staging
    unsigned int hkey[HASHSZ];              // open-addressing hash: key=(r<<13)|c
    float        hval[HASHSZ];              // cumulative delta per touched elem
    unsigned int list[LISTCAP];             // slots of distinct touched elems
    int          next_all[Kk];
    int          list_cnt;
    unsigned long long mbar[2];
};

__device__ __forceinline__ unsigned smem_u32(const void* p) {
    return (unsigned)__cvta_generic_to_shared(p);
}
__device__ __forceinline__ void mbar_init_(unsigned a, unsigned cnt) {
    asm volatile("mbarrier.init.shared::cta.b64 [%0], %1;" :: "r"(a), "r"(cnt) : "memory");
}
__device__ __forceinline__ void mbar_expect_tx_(unsigned a, unsigned bytes) {
    asm volatile("mbarrier.arrive.expect_tx.shared::cta.b64 _, [%0], %1;" :: "r"(a), "r"(bytes) : "memory");
}
__device__ __forceinline__ void mbar_wait_(unsigned a, unsigned parity) {
    asm volatile(
        "{\n\t.reg .pred P;\n"
        "LWAIT%=:\n\t"
        "mbarrier.try_wait.parity.shared::cta.b64 P, [%0], %1;\n\t"
        "@!P bra LWAIT%=;\n\t}"
        :: "r"(a), "r"(parity) : "memory");
}
__device__ __forceinline__ void bulk_g2s_(unsigned dst, const void* src, unsigned bytes, unsigned mbar) {
    asm volatile(
        "cp.async.bulk.shared::cluster.global.mbarrier::complete_tx::bytes [%0], [%1], %2, [%3];"
        :: "r"(dst), "l"(src), "r"(bytes), "r"(mbar) : "memory");
}

__device__ __forceinline__ unsigned long long pack_key(float v, int col) {
    unsigned vb = (v > 0.f) ? __float_as_uint(v) : 0u;   // relu; ties at 0 -> lower idx wins
    return ((unsigned long long)vb << 32) | (unsigned)(~(unsigned)col);
}
__device__ __forceinline__ int key_idx(unsigned long long k) {
    return (int)(~(unsigned)k);
}
__device__ __forceinline__ void insert6(unsigned long long* t, unsigned long long k) {
    if (k <= t[5]) return;
    t[5] = k;
    #pragma unroll
    for (int q = 5; q > 0; --q) {
        if (t[q] > t[q - 1]) {
            unsigned long long tmp = t[q]; t[q] = t[q - 1]; t[q - 1] = tmp;
        } else break;
    }
}
__device__ __forceinline__ void merge6(unsigned long long* a, const unsigned long long* b) {
    #pragma unroll
    for (int q = 0; q < 6; ++q) insert6(a, b[q]);
}

__device__ __forceinline__ unsigned hash_h(unsigned key) {
    return (key * 2654435761u) & (HASHSZ - 1);
}
__device__ float hash_get(ScanSmem* sm, int r, int c) {
    unsigned key = ((unsigned)r << 13) | (unsigned)c;
    unsigned h = hash_h(key);
    while (true) {
        unsigned k = sm->hkey[h];
        if (k == key) return sm->hval[h];
        if (k == 0xFFFFFFFFu) return 0.f;
        h = (h + 1) & (HASHSZ - 1);
    }
}
__device__ void hash_add(ScanSmem* sm, int r, int c, float d) {
    unsigned key = ((unsigned)r << 13) | (unsigned)c;
    unsigned h = hash_h(key);
    while (true) {
        unsigned k = sm->hkey[h];
        if (k == key) { atomicAdd(&sm->hval[h], d); return; }
        if (k == 0xFFFFFFFFu) {
            unsigned old = atomicCAS(&sm->hkey[h], 0xFFFFFFFFu, key);
            if (old == 0xFFFFFFFFu) {
                int li = atomicAdd(&sm->list_cnt, 1);
                sm->list[li] = h;
                atomicAdd(&sm->hval[h], d);
                return;
            }
            if (old == key) { atomicAdd(&sm->hval[h], d); return; }
            // another key claimed this slot; keep probing
        }
        h = (h + 1) & (HASHSZ - 1);
    }
}

// ---------------------------------------------------------------------------
// Kernel 2: sequential spark scan. Single CTA, 1024 threads.
// All W mutations tracked as additive deltas (hash). Rows streamed via TMA
// double-buffer. Epilogue writes pos/energy/age, s, and patched W elements.
// ---------------------------------------------------------------------------
__global__ void __launch_bounds__(1024, 1) scan_kernel(
    const float* __restrict__ W,
    const float* __restrict__ energy,
    const int*   __restrict__ spark_pos,
    const int*   __restrict__ spark_age,
    const int*   __restrict__ randint_vals,
    const int*   __restrict__ step_ptr,
    float*       __restrict__ out)
{
    extern __shared__ unsigned char smraw[];
    ScanSmem* sm = reinterpret_cast<ScanSmem*>(smraw);
    const int tid  = threadIdx.x;
    const int lane = tid & 31;
    const int wid  = tid >> 5;

    // init hash / control
    for (int i = tid; i < HASHSZ; i += 1024) { sm->hkey[i] = 0xFFFFFFFFu; sm->hval[i] = 0.f; }
    if (tid == 0) {
        sm->list_cnt = 0;
        mbar_init_(smem_u32(&sm->mbar[0]), 1);
        mbar_init_(smem_u32(&sm->mbar[1]), 1);
        asm volatile("fence.proxy.async.shared::cta;" ::: "memory");
    }
    // force young sparks: s[pos] = 1.0 where age < 5
    if (tid < Kk) {
        if (spark_age[tid] < 5) {
            int p = spark_pos[tid];
            if (p >= 0 && p < Nn) g_s[p] = 1.0f;
        }
    }
    __syncthreads();

    int step = step_ptr ? *step_ptr : 1;
    int mode = ((step % 3) + 3) % 3;

    // first row prefetch
    if (tid == 0) {
        unsigned mb = smem_u32(&sm->mbar[0]);
        mbar_expect_tx_(mb, Nn * 4u);
        bulk_g2s_(smem_u32(&sm->row[0][0]), W + (size_t)spark_pos[0] * Nn, Nn * 4u, mb);
    }

    for (int it = 0; it < Kk; ++it) {
        const int buf  = it & 1;
        const int prev = spark_pos[it];

        // prefetch next row (other buffer, fully consumed since prior iter's sync)
        if (tid == 0 && it + 1 < Kk) {
            unsigned mb = smem_u32(&sm->mbar[1 - buf]);
            mbar_expect_tx_(mb, Nn * 4u);
            bulk_g2s_(smem_u32(&sm->row[1 - buf][0]),
                      W + (size_t)spark_pos[it + 1] * Nn, Nn * 4u, mb);
        }
        // wait for this row
        mbar_wait_(smem_u32(&sm->mbar[buf]), (it >> 1) & 1);

        // apply accumulated deltas for this row onto the fresh base values
        int nl = sm->list_cnt;
        for (int j = tid; j < nl; j += 1024) {
            unsigned slot = sm->list[j];
            unsigned key  = sm->hkey[slot];
            if ((int)(key >> 13) == prev)
                sm->row[buf][key & (Nn - 1)] += sm->hval[slot];
        }
        __syncthreads();

        // local top-6 over 8 values/thread
        unsigned long long t[6];
        #pragma unroll
        for (int q = 0; q < 6; ++q) t[q] = 0ull;
        const float4* r4 = reinterpret_cast<const float4*>(&sm->row[buf][0]);
        #pragma unroll
        for (int g = 0; g < 2; ++g) {
            float4 v = r4[tid * 2 + g];
            int c0 = tid * 8 + g * 4;
            insert6(t, pack_key(v.x, c0));
            insert6(t, pack_key(v.y, c0 + 1));
            insert6(t, pack_key(v.z, c0 + 2));
            insert6(t, pack_key(v.w, c0 + 3));
        }
        // warp butterfly top-6
        #pragma unroll
        for (int off = 16; off; off >>= 1) {
            unsigned long long o[6];
            #pragma unroll
            for (int q = 0; q < 6; ++q) o[q] = __shfl_xor_sync(0xFFFFFFFFu, t[q], off);
            merge6(t, o);
        }
        if (lane == 0) {
            #pragma unroll
            for (int q = 0; q < 6; ++q) sm->warpTop[wid][q] = t[q];
        }
        __syncthreads();

        if (wid == 0) {
            #pragma unroll
            for (int q = 0; q < 6; ++q) t[q] = sm->warpTop[lane][q];
            #pragma unroll
            for (int off = 16; off; off >>= 1) {
                unsigned long long o[6];
                #pragma unroll
                for (int q = 0; q < 6; ++q) o[q] = __shfl_xor_sync(0xFFFFFFFFu, t[q], off);
                merge6(t, o);
            }
            // all warp-0 lanes now hold identical global top-6

            int next = (mode == 2) ? randint_vals[it] : key_idx(t[0]);

            float hnew = 0.f;
            if (lane == 0) {
                float cur = __ldg(&W[(size_t)next * Nn + prev]) + hash_get(sm, next, prev);
                float sp  = g_s[prev];
                hnew = cur * 0.95f + sp * 0.05f;         // Hebbian blend
                hash_add(sm, next, prev, hnew - cur);
                g_s[next] = energy[it] * 0.98f;          // s[next] = e_dec
                sm->next_all[it] = next;
            }
            hnew = __shfl_sync(0xFFFFFFFFu, hnew, 0);    // also orders hebbian before ripple

            // top-5 after Hebbian (only element (prev,prev) of this row can change)
            unsigned long long top5[5];
            if (next == prev) {
                unsigned long long cand[7];
                int cn = 0;
                #pragma unroll
                for (int q = 0; q < 6; ++q)
                    if (key_idx(t[q]) != prev) cand[cn++] = t[q];
                cand[cn++] = pack_key(hnew, prev);
                // insertion sort desc (cn <= 7)
                for (int a = 1; a < cn; ++a) {
                    unsigned long long kx = cand[a];
                    int b = a - 1;
                    while (b >= 0 && cand[b] < kx) { cand[b + 1] = cand[b]; --b; }
                    cand[b + 1] = kx;
                }
                #pragma unroll
                for (int q = 0; q < 5; ++q) top5[q] = cand[q];
            } else {
                #pragma unroll
                for (int q = 0; q < 5; ++q) top5[q] = t[q];
            }

            // ripple: 35 additive updates in parallel
            if (lane < 35) {
                int r, c; float d;
                if (lane < 5)       { r = prev;                  c = key_idx(top5[lane]);     d = 0.01f;  }
                else if (lane < 10) { r = key_idx(top5[lane-5]); c = prev;                    d = 0.005f; }
                else {
                    int a = (lane - 10) / 5, b = (lane - 10) % 5;
                    r = key_idx(top5[a]); c = key_idx(top5[b]); d = 0.003f;
                }
                hash_add(sm, r, c, d);
            }
        }
        __syncthreads();
    }

    // ------------------- epilogue: outputs -------------------
    const size_t oS = Kk;
    const size_t oW = (size_t)Kk + Nn;
    const size_t oE = oW + (size_t)Nn * Nn;
    const size_t oA = oE + Kk;

    if (tid < Kk) {
        float ed   = energy[tid] * 0.98f;
        bool reset = ed < 0.05f;
        int pn = reset ? (tid % Nn) : sm->next_all[tid];
        out[tid]      = (float)pn;
        out[oE + tid] = reset ? 1.0f : ed;
        out[oA + tid] = (float)(reset ? 0 : (spark_age[tid] + 1));
    }
    for (int j = tid; j < Nn; j += 1024) out[oS + j] = g_s[j];

    int nl = sm->list_cnt;
    for (int j = tid; j < nl; j += 1024) {
        unsigned slot = sm->list[j];
        unsigned key  = sm->hkey[slot];
        int r = (int)(key >> 13), c = (int)(key & (Nn - 1));
        float v = (W[(size_t)r * Nn + c] + sm->hval[slot]) * 0.999f;
        out[oW + (size_t)r * Nn + c] = fminf(fmaxf(v, -2.f), 2.f);
    }
}

// ---------------------------------------------------------------------------
// launch
// ---------------------------------------------------------------------------
extern "C" void kernel_launch(void* const* d_in, const int* in_sizes, int n_in,
                              void* d_out, int out_size)
{
    const float* W      = (const float*)d_in[0];
    const float* s      = (const float*)d_in[1];
    const float* noise  = (const float*)d_in[2];
    // d_in[3] = unif : unused (gumbel is a constant shift under argmax)
    const float* energy = (const float*)d_in[4];
    const int* spark_pos = (const int*)d_in[5];
    const int* spark_age = (const int*)d_in[6];
    const int* randint   = (const int*)d_in[7];
    const int* step      = (n_in > 8) ? (const int*)d_in[8] : nullptr;
    float* out = (float*)d_out;

    (void)in_sizes; (void)out_size;

    // Kernel 1: GEMV + decay copy (writes W section of out)
    gemv_decay_kernel<<<1024, 256>>>(W, s, noise, out + (Kk + Nn));

    // Kernel 2: sequential scan (single CTA, big dynamic smem)
    cudaFuncSetAttribute(scan_kernel, cudaFuncAttributeMaxDynamicSharedMemorySize,
                         (int)sizeof(ScanSmem));
    scan_kernel<<<1, 1024, sizeof(ScanSmem)>>>(W, energy, spark_pos, spark_age,
                                               randint, step, out);
}

// round 2
// speedup vs baseline: 2.0146x; 2.0146x over previous
#include <cuda_runtime.h>
#include <cstdint>
#include <cstddef>

#define Nn 8192
#define Kk 64
#define HASHSZ 8192
#define LISTCAP 2560
#define NBUF 4

// ---------------------------------------------------------------------------
// device globals (scratch; no allocation allowed)
// ---------------------------------------------------------------------------
__device__ float g_s[Nn];

// ---------------------------------------------------------------------------
// Kernel 1: fused GEMV (y = sigmoid(W @ (0.95*s) + 0.05*noise)) and
//           decay copy W_out = clip(W * 0.999, -2, 2).
// One warp per row. Reads W once (256MB), writes W_out once (256MB).
// ---------------------------------------------------------------------------
__global__ void __launch_bounds__(256) gemv_decay_kernel(
    const float* __restrict__ W,
    const float* __restrict__ s_in,
    const float* __restrict__ noise,
    float* __restrict__ Wout)
{
    const int warp = (blockIdx.x * blockDim.x + threadIdx.x) >> 5;
    const int lane = threadIdx.x & 31;
    if (warp >= Nn) return;

    const float4* wrow  = reinterpret_cast<const float4*>(W    + (size_t)warp * Nn);
    float4*       worow = reinterpret_cast<float4*>      (Wout + (size_t)warp * Nn);
    const float4* s4    = reinterpret_cast<const float4*>(s_in);

    float acc = 0.f;
    #pragma unroll 4
    for (int k = lane; k < Nn / 4; k += 32) {
        float4 w  = wrow[k];
        float4 sv = __ldg(&s4[k]);
        acc += w.x * (sv.x * 0.95f) + w.y * (sv.y * 0.95f)
             + w.z * (sv.z * 0.95f) + w.w * (sv.w * 0.95f);
        float4 o;
        o.x = fminf(fmaxf(w.x * 0.999f, -2.f), 2.f);
        o.y = fminf(fmaxf(w.y * 0.999f, -2.f), 2.f);
        o.z = fminf(fmaxf(w.z * 0.999f, -2.f), 2.f);
        o.w = fminf(fmaxf(w.w * 0.999f, -2.f), 2.f);
        __stcs(&worow[k], o);
    }
    #pragma unroll
    for (int off = 16; off; off >>= 1)
        acc += __shfl_xor_sync(0xFFFFFFFFu, acc, off);
    if (lane == 0) {
        float z = acc + 0.05f * noise[warp];
        g_s[warp] = 1.0f / (1.0f + expf(-z));
    }
}

// ---------------------------------------------------------------------------
// Scan shared memory
// ---------------------------------------------------------------------------
struct alignas(16) ScanSmem {
    float row[NBUF][Nn];                    // 4-deep TMA double-buffered rows
    unsigned long long warpTop[32][6];      // per-warp sorted top6
    unsigned int hkey[HASHSZ];
    float        hval[HASHSZ];
    unsigned int list[LISTCAP];
    int          next_all[Kk];
    int          list_cnt;
    unsigned long long mbar[NBUF];
};

__device__ __forceinline__ unsigned smem_u32(const void* p) {
    return (unsigned)__cvta_generic_to_shared(p);
}
__device__ __forceinline__ void mbar_init_(unsigned a, unsigned cnt) {
    asm volatile("mbarrier.init.shared::cta.b64 [%0], %1;" :: "r"(a), "r"(cnt) : "memory");
}
__device__ __forceinline__ void mbar_expect_tx_(unsigned a, unsigned bytes) {
    asm volatile("mbarrier.arrive.expect_tx.shared::cta.b64 _, [%0], %1;" :: "r"(a), "r"(bytes) : "memory");
}
__device__ __forceinline__ void mbar_wait_(unsigned a, unsigned parity) {
    asm volatile(
        "{\n\t.reg .pred P;\n"
        "LWAIT%=:\n\t"
        "mbarrier.try_wait.parity.shared::cta.b64 P, [%0], %1;\n\t"
        "@!P bra LWAIT%=;\n\t}"
        :: "r"(a), "r"(parity) : "memory");
}
__device__ __forceinline__ void bulk_g2s_(unsigned dst, const void* src, unsigned bytes, unsigned mbar) {
    asm volatile(
        "cp.async.bulk.shared::cluster.global.mbarrier::complete_tx::bytes [%0], [%1], %2, [%3];"
        :: "r"(dst), "l"(src), "r"(bytes), "r"(mbar) : "memory");
}

// key = relu-ordered float bits + 1 (so 0 == "excluded/none")
__device__ __forceinline__ unsigned valkey(float v) {
    return ((v > 0.f) ? __float_as_uint(v) : 0u) + 1u;
}
// 64-bit pack for candidate sorting: key desc, col asc
__device__ __forceinline__ unsigned long long pack64(unsigned key, int col) {
    return ((unsigned long long)key << 32) | (unsigned)(~(unsigned)col);
}
__device__ __forceinline__ int key_idx(unsigned long long k) {
    return (int)(~(unsigned)k);
}

__device__ __forceinline__ unsigned hash_h(unsigned key) {
    return (key * 2654435761u) & (HASHSZ - 1);
}
__device__ float hash_get(ScanSmem* sm, int r, int c) {
    unsigned key = ((unsigned)r << 13) | (unsigned)c;
    unsigned h = hash_h(key);
    while (true) {
        unsigned k = sm->hkey[h];
        if (k == key) return sm->hval[h];
        if (k == 0xFFFFFFFFu) return 0.f;
        h = (h + 1) & (HASHSZ - 1);
    }
}
__device__ void hash_add(ScanSmem* sm, int r, int c, float d) {
    unsigned key = ((unsigned)r << 13) | (unsigned)c;
    unsigned h = hash_h(key);
    while (true) {
        unsigned k = sm->hkey[h];
        if (k == key) { atomicAdd(&sm->hval[h], d); return; }
        if (k == 0xFFFFFFFFu) {
            unsigned old = atomicCAS(&sm->hkey[h], 0xFFFFFFFFu, key);
            if (old == 0xFFFFFFFFu) {
                int li = atomicAdd(&sm->list_cnt, 1);
                sm->list[li] = h;
                atomicAdd(&sm->hval[h], d);
                return;
            }
            if (old == key) { atomicAdd(&sm->hval[h], d); return; }
        }
        h = (h + 1) & (HASHSZ - 1);
    }
}

// ---------------------------------------------------------------------------
// Kernel 2: sequential spark scan. Single CTA, 1024 threads.
// ---------------------------------------------------------------------------
__global__ void __launch_bounds__(1024, 1) scan_kernel(
    const float* __restrict__ W,
    const float* __restrict__ energy,
    const int*   __restrict__ spark_pos,
    const int*   __restrict__ spark_age,
    const int*   __restrict__ randint_vals,
    const int*   __restrict__ step_ptr,
    float*       __restrict__ out)
{
    extern __shared__ unsigned char smraw[];
    ScanSmem* sm = reinterpret_cast<ScanSmem*>(smraw);
    const int tid  = threadIdx.x;
    const int lane = tid & 31;
    const int wid  = tid >> 5;

    for (int i = tid; i < HASHSZ; i += 1024) { sm->hkey[i] = 0xFFFFFFFFu; sm->hval[i] = 0.f; }
    if (tid == 0) {
        sm->list_cnt = 0;
        #pragma unroll
        for (int b = 0; b < NBUF; ++b) mbar_init_(smem_u32(&sm->mbar[b]), 1);
        asm volatile("fence.proxy.async.shared::cta;" ::: "memory");
        // prefetch first NBUF-1 rows
        for (int r = 0; r < NBUF - 1 && r < Kk; ++r) {
            unsigned mb = smem_u32(&sm->mbar[r]);
            mbar_expect_tx_(mb, Nn * 4u);
            bulk_g2s_(smem_u32(&sm->row[r][0]), W + (size_t)spark_pos[r] * Nn, Nn * 4u, mb);
        }
    }
    // force young sparks: s[pos] = 1.0 where age < 5
    if (tid < Kk) {
        if (spark_age[tid] < 5) {
            int p = spark_pos[tid];
            if (p >= 0 && p < Nn) g_s[p] = 1.0f;
        }
    }
    __syncthreads();

    int step = step_ptr ? *step_ptr : 1;
    int mode = ((step % 3) + 3) % 3;

    const int cbase = (wid << 8) + (lane << 3);   // this lane's 8-element column base

    for (int it = 0; it < Kk; ++it) {
        const int buf  = it & (NBUF - 1);
        const int prev = spark_pos[it];

        // prefetch row it+NBUF-1 into the buffer freed at the end of iter it-1
        if (tid == 0 && it + NBUF - 1 < Kk) {
            int pf = it + NBUF - 1;
            unsigned mb = smem_u32(&sm->mbar[pf & (NBUF - 1)]);
            mbar_expect_tx_(mb, Nn * 4u);
            bulk_g2s_(smem_u32(&sm->row[pf & (NBUF - 1)][0]),
                      W + (size_t)spark_pos[pf] * Nn, Nn * 4u, mb);
        }
        mbar_wait_(smem_u32(&sm->mbar[buf]), (it >> 2) & 1);

        // apply accumulated deltas for this row
        int nl = sm->list_cnt;
        for (int j = tid; j < nl; j += 1024) {
            unsigned slot = sm->list[j];
            unsigned key  = sm->hkey[slot];
            if ((int)(key >> 13) == prev)
                sm->row[buf][key & (Nn - 1)] += sm->hval[slot];
        }
        __syncthreads();

        // ---- per-warp top-6 over its 256-element chunk (no CTA barriers) ----
        const float4* r4 = reinterpret_cast<const float4*>(&sm->row[buf][0]);
        float4 va = r4[(cbase >> 2)];
        float4 vb = r4[(cbase >> 2) + 1];
        unsigned k0 = valkey(va.x), k1 = valkey(va.y), k2 = valkey(va.z), k3 = valkey(va.w);
        unsigned k4 = valkey(vb.x), k5 = valkey(vb.y), k6 = valkey(vb.z), k7 = valkey(vb.w);

        unsigned long long wt[6];
        #pragma unroll
        for (int p = 0; p < 6; ++p) {
            unsigned bk = k0; int bj = 0;
            if (k1 > bk) { bk = k1; bj = 1; }
            if (k2 > bk) { bk = k2; bj = 2; }
            if (k3 > bk) { bk = k3; bj = 3; }
            if (k4 > bk) { bk = k4; bj = 4; }
            if (k5 > bk) { bk = k5; bj = 5; }
            if (k6 > bk) { bk = k6; bj = 6; }
            if (k7 > bk) { bk = k7; bj = 7; }
            unsigned kmax = __reduce_max_sync(0xFFFFFFFFu, bk);
            unsigned cand = (bk == kmax) ? (unsigned)(cbase + bj) : 0xFFFFFFFFu;
            unsigned cmin = __reduce_min_sync(0xFFFFFFFFu, cand);
            wt[p] = pack64(kmax, (int)cmin);
            int rel = (int)cmin - cbase;
            if (rel >= 0 && rel < 8) {
                if (rel == 0) k0 = 0; if (rel == 1) k1 = 0;
                if (rel == 2) k2 = 0; if (rel == 3) k3 = 0;
                if (rel == 4) k4 = 0; if (rel == 5) k5 = 0;
                if (rel == 6) k6 = 0; if (rel == 7) k7 = 0;
            }
        }
        if (lane == 0) {
            #pragma unroll
            for (int p = 0; p < 6; ++p) sm->warpTop[wid][p] = wt[p];
        }
        __syncthreads();

        // ---- warp 0: merge 32 sorted 6-lists, leader updates ----
        if (wid == 0) {
            unsigned long long e0 = sm->warpTop[lane][0];
            unsigned long long e1 = sm->warpTop[lane][1];
            unsigned long long e2 = sm->warpTop[lane][2];
            unsigned long long e3 = sm->warpTop[lane][3];
            unsigned long long e4 = sm->warpTop[lane][4];
            unsigned long long e5 = sm->warpTop[lane][5];
            int ptr = 0;
            unsigned long long t[6];
            #pragma unroll
            for (int p = 0; p < 6; ++p) {
                unsigned long long cur = e0;
                if (ptr == 1) cur = e1;
                if (ptr == 2) cur = e2;
                if (ptr == 3) cur = e3;
                if (ptr == 4) cur = e4;
                if (ptr == 5) cur = e5;
                unsigned hi = (unsigned)(cur >> 32);
                unsigned kmax = __reduce_max_sync(0xFFFFFFFFu, hi);
                unsigned locand = (hi == kmax) ? (unsigned)cur : 0u;
                unsigned lomax = __reduce_max_sync(0xFFFFFFFFu, locand);
                t[p] = ((unsigned long long)kmax << 32) | lomax;
                if (hi == kmax && (unsigned)cur == lomax) ptr++;
            }

            int next = (mode == 2) ? randint_vals[it] : key_idx(t[0]);

            float hnew = 0.f;
            if (lane == 0) {
                float cur = __ldg(&W[(size_t)next * Nn + prev]) + hash_get(sm, next, prev);
                float sp  = g_s[prev];
                hnew = cur * 0.95f + sp * 0.05f;
                hash_add(sm, next, prev, hnew - cur);
                g_s[next] = energy[it] * 0.98f;
                sm->next_all[it] = next;
            }
            hnew = __shfl_sync(0xFFFFFFFFu, hnew, 0);   // also orders hebbian before ripple

            // top-5 after Hebbian: only in-row element (prev,prev) can change
            unsigned long long top5[5];
            if (next == prev) {
                unsigned long long cand[7];
                int cn = 0;
                #pragma unroll
                for (int q = 0; q < 6; ++q)
                    if (key_idx(t[q]) != prev) cand[cn++] = t[q];
                cand[cn++] = pack64(valkey(hnew), prev);
                for (int a = 1; a < cn; ++a) {
                    unsigned long long kx = cand[a];
                    int b = a - 1;
                    while (b >= 0 && cand[b] < kx) { cand[b + 1] = cand[b]; --b; }
                    cand[b + 1] = kx;
                }
                #pragma unroll
                for (int q = 0; q < 5; ++q) top5[q] = cand[q];
            } else {
                #pragma unroll
                for (int q = 0; q < 5; ++q) top5[q] = t[q];
            }

            // ripple: 35 additive updates (fixed: all 35, not 32)
            for (int u = lane; u < 35; u += 32) {
                int r, c; float d;
                if (u < 5)       { r = prev;                c = key_idx(top5[u]);   d = 0.01f;  }
                else if (u < 10) { r = key_idx(top5[u-5]);  c = prev;               d = 0.005f; }
                else {
                    int a = (u - 10) / 5, b = (u - 10) % 5;
                    r = key_idx(top5[a]); c = key_idx(top5[b]); d = 0.003f;
                }
                hash_add(sm, r, c, d);
            }
        }
        __syncthreads();
    }

    // ------------------- epilogue -------------------
    const size_t oS = Kk;
    const size_t oW = (size_t)Kk + Nn;
    const size_t oE = oW + (size_t)Nn * Nn;
    const size_t oA = oE + Kk;

    if (tid < Kk) {
        float ed   = energy[tid] * 0.98f;
        bool reset = ed < 0.05f;
        int pn = reset ? (tid % Nn) : sm->next_all[tid];
        out[tid]      = (float)pn;
        out[oE + tid] = reset ? 1.0f : ed;
        out[oA + tid] = (float)(reset ? 0 : (spark_age[tid] + 1));
    }
    for (int j = tid; j < Nn; j += 1024) out[oS + j] = g_s[j];

    int nl = sm->list_cnt;
    for (int j = tid; j < nl; j += 1024) {
        unsigned slot = sm->list[j];
        unsigned key  = sm->hkey[slot];
        int r = (int)(key >> 13), c = (int)(key & (Nn - 1));
        float v = (W[(size_t)r * Nn + c] + sm->hval[slot]) * 0.999f;
        out[oW + (size_t)r * Nn + c] = fminf(fmaxf(v, -2.f), 2.f);
    }
}

// ---------------------------------------------------------------------------
// launch
// ---------------------------------------------------------------------------
extern "C" void kernel_launch(void* const* d_in, const int* in_sizes, int n_in,
                              void* d_out, int out_size)
{
    const float* W      = (const float*)d_in[0];
    const float* s      = (const float*)d_in[1];
    const float* noise  = (const float*)d_in[2];
    // d_in[3] = unif : unused (scalar gumbel shift doesn't change argmax)
    const float* energy = (const float*)d_in[4];
    const int* spark_pos = (const int*)d_in[5];
    const int* spark_age = (const int*)d_in[6];
    const int* randint   = (const int*)d_in[7];
    const int* step      = (n_in > 8) ? (const int*)d_in[8] : nullptr;
    float* out = (float*)d_out;

    (void)in_sizes; (void)out_size;

    gemv_decay_kernel<<<1024, 256>>>(W, s, noise, out + (Kk + Nn));

    cudaFuncSetAttribute(scan_kernel, cudaFuncAttributeMaxDynamicSharedMemorySize,
                         (int)sizeof(ScanSmem));
    scan_kernel<<<1, 1024, sizeof(ScanSmem)>>>(W, energy, spark_pos, spark_age,
                                               randint, step, out);
}

// round 3
// speedup vs baseline: 2.4790x; 1.2305x over previous
#include <cuda_runtime.h>
#include <cstdint>
#include <cstddef>

#define Nn 8192
#define Kk 64
#define RR 64                  // base top-R per spark row
#define HASHSZ 8192
#define LISTCAP 2368
#define CANDCAP (RR + LISTCAP)

// ---------------------------------------------------------------------------
// device globals
// ---------------------------------------------------------------------------
__device__ float g_s[Nn];
__device__ unsigned long long g_top[Kk][RR];

// ---------------------------------------------------------------------------
// key packing: (relu-ordered value bits + 1) << 32 | ~col   (desc val, asc col)
// ---------------------------------------------------------------------------
__device__ __forceinline__ unsigned valkey(float v) {
    return ((v > 0.f) ? __float_as_uint(v) : 0u) + 1u;
}
__device__ __forceinline__ unsigned long long pack64(unsigned key, int col) {
    return ((unsigned long long)key << 32) | (unsigned)(~(unsigned)col);
}
__device__ __forceinline__ int key_idx(unsigned long long k) {
    return (int)(~(unsigned)k);
}

// ---------------------------------------------------------------------------
// Prep kernel: blocks 0..63 compute base top-64 of row spark_pos[b] first,
// then ALL blocks do warp-per-row GEMV + decay-copy.
// grid = 296 blocks x 1024 threads (gemv warps = 9472 >= 8192 rows)
// ---------------------------------------------------------------------------
__global__ void __launch_bounds__(1024) prep_kernel(
    const float* __restrict__ W,
    const float* __restrict__ s_in,
    const float* __restrict__ noise,
    const int*   __restrict__ spark_pos,
    float*       __restrict__ Wout)
{
    __shared__ unsigned long long wl[32][RR];
    const int tid  = threadIdx.x;
    const int lane = tid & 31;
    const int wid  = tid >> 5;

    if (blockIdx.x < Kk) {
        // ---------- Phase A: base top-64 of this spark's row ----------
        const int row = spark_pos[blockIdx.x];
        const float4* r4 = reinterpret_cast<const float4*>(W + (size_t)row * Nn);
        const int cbase = (wid << 8) + (lane << 3);
        float4 a = __ldg(&r4[cbase >> 2]);
        float4 b = __ldg(&r4[(cbase >> 2) + 1]);
        unsigned k0 = valkey(a.x), k1 = valkey(a.y), k2 = valkey(a.z), k3 = valkey(a.w);
        unsigned k4 = valkey(b.x), k5 = valkey(b.y), k6 = valkey(b.z), k7 = valkey(b.w);

        for (int p = 0; p < RR; ++p) {
            unsigned bk = k0; int bj = 0;
            if (k1 > bk) { bk = k1; bj = 1; }
            if (k2 > bk) { bk = k2; bj = 2; }
            if (k3 > bk) { bk = k3; bj = 3; }
            if (k4 > bk) { bk = k4; bj = 4; }
            if (k5 > bk) { bk = k5; bj = 5; }
            if (k6 > bk) { bk = k6; bj = 6; }
            if (k7 > bk) { bk = k7; bj = 7; }
            unsigned kmax = __reduce_max_sync(0xFFFFFFFFu, bk);
            unsigned cand = (bk == kmax) ? (unsigned)(cbase + bj) : 0xFFFFFFFFu;
            unsigned cmin = __reduce_min_sync(0xFFFFFFFFu, cand);
            if (lane == 0) wl[wid][p] = pack64(kmax, (int)cmin);
            int rel = (int)cmin - cbase;
            if (rel >= 0 && rel < 8) {
                if (rel == 0) k0 = 0; if (rel == 1) k1 = 0;
                if (rel == 2) k2 = 0; if (rel == 3) k3 = 0;
                if (rel == 4) k4 = 0; if (rel == 5) k5 = 0;
                if (rel == 6) k6 = 0; if (rel == 7) k7 = 0;
            }
        }
        __syncthreads();
        if (wid == 0) {
            int head = 0;
            for (int p = 0; p < RR; ++p) {
                unsigned long long cur = (head < RR) ? wl[lane][head] : 0ull;
                unsigned hi = (unsigned)(cur >> 32);
                unsigned kmax = __reduce_max_sync(0xFFFFFFFFu, hi);     // >=1 always
                unsigned lo = (hi == kmax) ? (unsigned)cur : 0u;
                unsigned lomax = __reduce_max_sync(0xFFFFFFFFu, lo);
                if (hi == kmax && (unsigned)cur == lomax) head++;
                if (lane == 0)
                    g_top[blockIdx.x][p] = ((unsigned long long)kmax << 32) | lomax;
            }
        }
        __syncthreads();
    }

    // ---------- GEMV + decay-copy: warp per row ----------
    const int gw = blockIdx.x * 32 + wid;
    if (gw < Nn) {
        const float4* wrow  = reinterpret_cast<const float4*>(W    + (size_t)gw * Nn);
        float4*       worow = reinterpret_cast<float4*>      (Wout + (size_t)gw * Nn);
        const float4* s4    = reinterpret_cast<const float4*>(s_in);
        float acc = 0.f;
        #pragma unroll 4
        for (int k = lane; k < Nn / 4; k += 32) {
            float4 w  = __ldcs(&wrow[k]);
            float4 sv = __ldg(&s4[k]);
            acc += w.x * (sv.x * 0.95f) + w.y * (sv.y * 0.95f)
                 + w.z * (sv.z * 0.95f) + w.w * (sv.w * 0.95f);
            float4 o;
            o.x = fminf(fmaxf(w.x * 0.999f, -2.f), 2.f);
            o.y = fminf(fmaxf(w.y * 0.999f, -2.f), 2.f);
            o.z = fminf(fmaxf(w.z * 0.999f, -2.f), 2.f);
            o.w = fminf(fmaxf(w.w * 0.999f, -2.f), 2.f);
            __stcs(&worow[k], o);
        }
        #pragma unroll
        for (int off = 16; off; off >>= 1)
            acc += __shfl_xor_sync(0xFFFFFFFFu, acc, off);
        if (lane == 0) {
            float z = acc + 0.05f * noise[gw];
            g_s[gw] = 1.0f / (1.0f + expf(-z));
        }
    }
}

// ---------------------------------------------------------------------------
// Scan shared memory
// ---------------------------------------------------------------------------
struct alignas(16) SS {
    float s[Nn];                          // 32KB state vector
    unsigned long long top[Kk][RR];       // 32KB base top lists
    unsigned hkey[HASHSZ];                // 32KB
    float    hval[HASHSZ];                // 32KB (cumulative delta)
    float    hbase[HASHSZ];               // 32KB (base W value; NaN = unfilled)
    unsigned list[LISTCAP];
    unsigned long long cand[CANDCAP];
    float spec[32];                       // speculative W[c][prev] prefetch
    int   spp[Kk]; float sen[Kk]; int srnd[Kk];
    int   next_all[Kk];
    int   list_cnt;
    int   mcnt;
};

__device__ __forceinline__ unsigned hash_h(unsigned key) {
    return (key * 2654435761u) & (HASHSZ - 1);
}
__device__ __forceinline__ int hfind(SS* sm, unsigned key) {
    unsigned h = hash_h(key);
    while (true) {
        unsigned k = sm->hkey[h];
        if (k == key) return (int)h;
        if (k == 0xFFFFFFFFu) return -1;
        h = (h + 1) & (HASHSZ - 1);
    }
}
__device__ void hadd(SS* sm, unsigned key, float d) {
    unsigned h = hash_h(key);
    while (true) {
        unsigned k = sm->hkey[h];
        if (k == key) { atomicAdd(&sm->hval[h], d); return; }
        if (k == 0xFFFFFFFFu) {
            unsigned old = atomicCAS(&sm->hkey[h], 0xFFFFFFFFu, key);
            if (old == 0xFFFFFFFFu) {
                sm->hbase[h] = __int_as_float(0x7fffffff);   // NaN = lazy base
                int li = atomicAdd(&sm->list_cnt, 1);
                sm->list[li] = h;
                atomicAdd(&sm->hval[h], d);
                return;
            }
            if (old == key) { atomicAdd(&sm->hval[h], d); return; }
        }
        h = (h + 1) & (HASHSZ - 1);
    }
}

__device__ __forceinline__ void cp_async4(void* smem_dst, const void* gptr) {
    unsigned a = (unsigned)__cvta_generic_to_shared(smem_dst);
    asm volatile("cp.async.ca.shared.global [%0], [%1], 4;" :: "r"(a), "l"(gptr) : "memory");
}

// ---------------------------------------------------------------------------
// Kernel 2: sequential spark scan. Single CTA, 256 threads.
// ---------------------------------------------------------------------------
__global__ void __launch_bounds__(256, 1) scan_kernel(
    const float* __restrict__ W,
    const float* __restrict__ energy,
    const int*   __restrict__ spark_pos,
    const int*   __restrict__ spark_age,
    const int*   __restrict__ randint_vals,
    const int*   __restrict__ step_ptr,
    float*       __restrict__ out)
{
    extern __shared__ unsigned char smraw[];
    SS* sm = reinterpret_cast<SS*>(smraw);
    const int tid  = threadIdx.x;
    const int lane = tid & 31;
    const int wid  = tid >> 5;

    // ---- init ----
    for (int i = tid; i < Nn; i += 256) sm->s[i] = g_s[i];
    {
        unsigned long long* td = &sm->top[0][0];
        const unsigned long long* tsrc = &g_top[0][0];
        for (int i = tid; i < Kk * RR; i += 256) td[i] = tsrc[i];
    }
    for (int i = tid; i < HASHSZ; i += 256) { sm->hkey[i] = 0xFFFFFFFFu; sm->hval[i] = 0.f; }
    if (tid < Kk) {
        sm->spp[tid]  = spark_pos[tid];
        sm->sen[tid]  = energy[tid];
        sm->srnd[tid] = randint_vals[tid];
    }
    if (tid == 0) { sm->list_cnt = 0; sm->mcnt = 0; }
    __syncthreads();
    if (tid < Kk) {                               // force young sparks
        if (spark_age[tid] < 5) {
            int p = sm->spp[tid];
            if (p >= 0 && p < Nn) sm->s[p] = 1.0f;
        }
    }
    __syncthreads();

    const int step = step_ptr ? *step_ptr : 1;
    const int mode = ((step % 3) + 3) % 3;

    for (int it = 0; it < Kk; ++it) {
        const int prev = sm->spp[it];

        // ================= stage 1 =================
        if (wid == 0) {
            // speculative base prefetch of W[c][prev] for likely 'next'
            if (mode != 2) {
                int c = key_idx(sm->top[it][lane]);
                cp_async4(&sm->spec[lane], W + (size_t)c * Nn + prev);
            } else if (lane == 0) {
                cp_async4(&sm->spec[0], W + (size_t)sm->srnd[it] * Nn + prev);
            }
            asm volatile("cp.async.commit_group;" ::: "memory");
        } else if (wid == 1) {
            // base-list exclusion: zero entries whose col is delta-touched
            #pragma unroll
            for (int q = 0; q < 2; ++q) {
                int j = lane + 32 * q;
                unsigned long long e = sm->top[it][j];
                int c = key_idx(e);
                sm->cand[j] = (hfind(sm, ((unsigned)prev << 13) | (unsigned)c) >= 0) ? 0ull : e;
            }
        } else {
            // gather touched entries of this row with current values
            int nl = sm->list_cnt;
            for (int j = tid - 64; j < nl; j += 192) {
                unsigned slot = sm->list[j];
                unsigned key  = sm->hkey[slot];
                if ((int)(key >> 13) == prev) {
                    int c = (int)(key & (Nn - 1));
                    float b = sm->hbase[slot];
                    if (b != b) { b = __ldg(&W[(size_t)prev * Nn + c]); sm->hbase[slot] = b; }
                    float v = b + sm->hval[slot];
                    int ix = atomicAdd(&sm->mcnt, 1);
                    sm->cand[RR + ix] = pack64(valkey(v), c);
                }
            }
        }
        __syncthreads();

        // ================= stage 2 (warp 0) =================
        if (wid == 0) {
            const int nc = RR + sm->mcnt;
            unsigned long long mine[4];
            #pragma unroll
            for (int q = 0; q < 4; ++q) {
                int idx = lane + 32 * q;
                mine[q] = (idx < nc) ? sm->cand[idx] : 0ull;
            }
            const bool ext = nc > 128;

            unsigned long long t[6];
            #pragma unroll
            for (int p = 0; p < 6; ++p) {
                unsigned long long b = mine[0];
                if (mine[1] > b) b = mine[1];
                if (mine[2] > b) b = mine[2];
                if (mine[3] > b) b = mine[3];
                if (ext)
                    for (int j = 128 + lane; j < nc; j += 32) {
                        unsigned long long v = sm->cand[j];
                        if (v > b) b = v;
                    }
                unsigned hi = (unsigned)(b >> 32);
                unsigned himax = __reduce_max_sync(0xFFFFFFFFu, hi);
                unsigned lo = (hi == himax) ? (unsigned)b : 0u;
                unsigned lomax = __reduce_max_sync(0xFFFFFFFFu, lo);
                unsigned long long win = ((unsigned long long)himax << 32) | lomax;
                t[p] = win;
                #pragma unroll
                for (int q = 0; q < 4; ++q) if (mine[q] == win) mine[q] = 0ull;
                if (ext)
                    for (int j = 128 + lane; j < nc; j += 32)
                        if (sm->cand[j] == win) sm->cand[j] = 0ull;
            }

            const int next = (mode == 2) ? sm->srnd[it] : key_idx(t[0]);

            // spec-match ballot (all lanes)
            int myc = (mode != 2) ? key_idx(sm->top[it][lane]) : -1;
            unsigned mmask = __ballot_sync(0xFFFFFFFFu, myc == next);
            asm volatile("cp.async.wait_group 0;" ::: "memory");

            float hnew = 0.f;
            if (lane == 0) {
                unsigned key = ((unsigned)next << 13) | (unsigned)prev;
                int slot = hfind(sm, key);
                float base; bool have = false;
                if (slot >= 0) {
                    float b = sm->hbase[slot];
                    if (b == b) { base = b; have = true; }
                }
                if (!have) {
                    if (mode == 2)       base = sm->spec[0];
                    else if (mmask)      base = sm->spec[__ffs(mmask) - 1];
                    else                 base = __ldg(&W[(size_t)next * Nn + prev]);
                }
                float cur = base + ((slot >= 0) ? sm->hval[slot] : 0.f);
                float sp  = sm->s[prev];
                hnew = cur * 0.95f + sp * 0.05f;
                if (slot >= 0) {
                    sm->hbase[slot] = base;
                    sm->hval[slot] += hnew - cur;
                } else {
                    unsigned h = hash_h(key);
                    while (sm->hkey[h] != 0xFFFFFFFFu) h = (h + 1) & (HASHSZ - 1);
                    sm->hkey[h]  = key;
                    sm->hbase[h] = base;
                    sm->hval[h]  = hnew - base;
                    int li = sm->list_cnt; sm->list[li] = h; sm->list_cnt = li + 1;
                }
                sm->s[next] = sm->sen[it] * 0.98f;
                sm->next_all[it] = next;
                sm->mcnt = 0;
            }
            hnew = __shfl_sync(0xFFFFFFFFu, hnew, 0);

            // top-5 after Hebbian: only in-row element (prev,prev) can change
            unsigned long long top5[5];
            if (next == prev) {
                unsigned long long cnd[7];
                int cn = 0;
                #pragma unroll
                for (int q = 0; q < 6; ++q)
                    if (key_idx(t[q]) != prev) cnd[cn++] = t[q];
                cnd[cn++] = pack64(valkey(hnew), prev);
                for (int a = 1; a < cn; ++a) {
                    unsigned long long kx = cnd[a];
                    int b = a - 1;
                    while (b >= 0 && cnd[b] < kx) { cnd[b + 1] = cnd[b]; --b; }
                    cnd[b + 1] = kx;
                }
                #pragma unroll
                for (int q = 0; q < 5; ++q) top5[q] = cnd[q];
            } else {
                #pragma unroll
                for (int q = 0; q < 5; ++q) top5[q] = t[q];
            }

            // ripple: 35 additive updates
            for (int u = lane; u < 35; u += 32) {
                int r, c; float d;
                if (u < 5)       { r = prev;                c = key_idx(top5[u]);   d = 0.01f;  }
                else if (u < 10) { r = key_idx(top5[u-5]);  c = prev;               d = 0.005f; }
                else {
                    int a = (u - 10) / 5, b2 = (u - 10) % 5;
                    r = key_idx(top5[a]); c = key_idx(top5[b2]); d = 0.003f;
                }
                hadd(sm, ((unsigned)r << 13) | (unsigned)c, d);
            }
        }
        __syncthreads();
    }

    // ------------------- epilogue -------------------
    const size_t oS = Kk;
    const size_t oW = (size_t)Kk + Nn;
    const size_t oE = oW + (size_t)Nn * Nn;
    const size_t oA = oE + Kk;

    if (tid < Kk) {
        float ed   = sm->sen[tid] * 0.98f;
        bool reset = ed < 0.05f;
        int pn = reset ? (tid % Nn) : sm->next_all[tid];
        out[tid]      = (float)pn;
        out[oE + tid] = reset ? 1.0f : ed;
        out[oA + tid] = (float)(reset ? 0 : (spark_age[tid] + 1));
    }
    for (int j = tid; j < Nn; j += 256) out[oS + j] = sm->s[j];

    int nl = sm->list_cnt;
    for (int j = tid; j < nl; j += 256) {
        unsigned slot = sm->list[j];
        unsigned key  = sm->hkey[slot];
        int r = (int)(key >> 13), c = (int)(key & (Nn - 1));
        float b = sm->hbase[slot];
        if (b != b) b = __ldg(&W[(size_t)r * Nn + c]);
        float v = (b + sm->hval[slot]) * 0.999f;
        out[oW + (size_t)r * Nn + c] = fminf(fmaxf(v, -2.f), 2.f);
    }
}

// ---------------------------------------------------------------------------
// launch
// ---------------------------------------------------------------------------
extern "C" void kernel_launch(void* const* d_in, const int* in_sizes, int n_in,
                              void* d_out, int out_size)
{
    const float* W      = (const float*)d_in[0];
    const float* s      = (const float*)d_in[1];
    const float* noise  = (const float*)d_in[2];
    // d_in[3] = unif : unused (scalar gumbel shift doesn't change argmax)
    const float* energy = (const float*)d_in[4];
    const int* spark_pos = (const int*)d_in[5];
    const int* spark_age = (const int*)d_in[6];
    const int* randint   = (const int*)d_in[7];
    const int* step      = (n_in > 8) ? (const int*)d_in[8] : nullptr;
    float* out = (float*)d_out;

    (void)in_sizes; (void)out_size;

    prep_kernel<<<296, 1024>>>(W, s, noise, spark_pos, out + (Kk + Nn));

    cudaFuncSetAttribute(scan_kernel, cudaFuncAttributeMaxDynamicSharedMemorySize,
                         (int)sizeof(SS));
    scan_kernel<<<1, 256, sizeof(SS)>>>(W, energy, spark_pos, spark_age,
                                        randint, step, out);
}